// round 15
// baseline (speedup 1.0000x reference)
#include <cuda_runtime.h>
#include <cuda_fp16.h>
#include <math.h>
#include <stdint.h>

#define B_ 2
#define T_ 2048
#define C_ 1024
#define H_ 16
#define D_ 64

// ---------------- scratch (allocation-free rule: __device__ globals) --------
__device__ __half g_xh[(size_t)B_ * T_ * C_];
__device__ __half g_wqh[(size_t)C_ * 3 * C_];
__device__ __half g_wph[(size_t)C_ * C_];
__device__ __half g_qkvh[(size_t)B_ * T_ * 3 * C_];
__device__ __half g_ath[(size_t)B_ * T_ * C_];

// ---------------- helpers ----------------------------------------------------
__device__ __forceinline__ uint32_t smem_u32(const void* p) {
    uint32_t a;
    asm("{ .reg .u64 t; cvta.to.shared.u64 t, %1; cvt.u32.u64 %0, t; }"
        : "=r"(a) : "l"(p));
    return a;
}
__device__ __forceinline__ void ldsm_x4(uint32_t* r, uint32_t addr) {
    asm volatile("ldmatrix.sync.aligned.m8n8.x4.shared.b16 {%0,%1,%2,%3}, [%4];"
                 : "=r"(r[0]), "=r"(r[1]), "=r"(r[2]), "=r"(r[3]) : "r"(addr));
}
__device__ __forceinline__ void ldsm_x4_t(uint32_t* r, uint32_t addr) {
    asm volatile("ldmatrix.sync.aligned.m8n8.x4.trans.shared.b16 {%0,%1,%2,%3}, [%4];"
                 : "=r"(r[0]), "=r"(r[1]), "=r"(r[2]), "=r"(r[3]) : "r"(addr));
}
__device__ __forceinline__ void mma16816(float* d, const uint32_t* a,
                                         uint32_t b0, uint32_t b1) {
    asm volatile(
        "mma.sync.aligned.m16n8k16.row.col.f32.f16.f16.f32 "
        "{%0,%1,%2,%3}, {%4,%5,%6,%7}, {%8,%9}, {%0,%1,%2,%3};"
        : "+f"(d[0]), "+f"(d[1]), "+f"(d[2]), "+f"(d[3])
        : "r"(a[0]), "r"(a[1]), "r"(a[2]), "r"(a[3]), "r"(b0), "r"(b1));
}
__device__ __forceinline__ void cp16(uint32_t dst, const void* src) {
    asm volatile("cp.async.cg.shared.global [%0], [%1], 16;" :: "r"(dst), "l"(src));
}
#define CP_COMMIT() asm volatile("cp.async.commit_group;" ::: "memory")
#define CP_WAIT(n)  asm volatile("cp.async.wait_group %0;" :: "n"(n) : "memory")

__device__ __forceinline__ uint32_t pkh2(float a, float b) {
    __half2 t = __floats2half2_rn(a, b);
    return *reinterpret_cast<uint32_t*>(&t);
}

// ---------------- fused fp32 -> fp16 convert (x, w_qkv, w_proj) -------------
#define N4_X  (B_ * T_ * C_ / 4)
#define N4_WQ (C_ * 3 * C_ / 4)
#define N4_WP (C_ * C_ / 4)

__global__ __launch_bounds__(256) void cvt_all_kernel(
    const float* __restrict__ x, const float* __restrict__ wq,
    const float* __restrict__ wp, __half* __restrict__ xh,
    __half* __restrict__ wqh, __half* __restrict__ wph)
{
    int i = blockIdx.x * blockDim.x + threadIdx.x;
    const float* src;
    __half* dst;
    if (i < N4_X) { src = x; dst = xh; }
    else if (i < N4_X + N4_WQ) { i -= N4_X; src = wq; dst = wqh; }
    else { i -= N4_X + N4_WQ; src = wp; dst = wph; if (i >= N4_WP) return; }
    const float4 f = ((const float4*)src)[i];
    ((uint2*)dst)[i] = make_uint2(pkh2(f.x, f.y), pkh2(f.z, f.w));
}

// ---------------------------------------------------------------------------
// Single-pass fp16 GEMM (fp32 accum): C = A @ B. CTA tile 128x64, BK=32,
// 128 threads = 4 warps stacked in M (warp tile 32x64 IDENTICAL to proven
// config), 3-stage cp.async, 4 CTAs/SM. Finer granularity -> better makespan.
// ---------------------------------------------------------------------------
#define G_A  0
#define G_B  10240                    /* 128 rows * 80B */
#define G_STAGE 14848                 /* + 32 rows * 144B */
#define G_NSTAGE 3
#define GEMM_SMEM (G_NSTAGE * G_STAGE)   /* 44544 B; x4 CTAs = 174KB */

template<int HALF_OUT>
__global__ __launch_bounds__(128, 4) void gemm_fp16(
    const __half* __restrict__ Ah, const __half* __restrict__ Bh,
    float* __restrict__ Cf, __half* __restrict__ Ch, int M, int N, int K)
{
    extern __shared__ __align__(128) char smem[];
    const uint32_t sb = smem_u32(smem);

    const int tid = threadIdx.x;
    const int wid = tid >> 5, lane = tid & 31;
    const int bm = blockIdx.y * 128, bn = blockIdx.x * 64;
    const int wm = wid * 32;                 // 4 warps stacked in M

    const int a_r = wm + (lane & 15);
    const int a_c = (lane >> 4) * 8;
    const uint32_t b_row = (uint32_t)(((lane >> 3) & 1) * 8 + (lane & 7));
    const uint32_t b_colb = (uint32_t)((lane >> 4) * 8) * 2;

    float acc[2][8][4];
    #pragma unroll
    for (int mi = 0; mi < 2; ++mi)
        #pragma unroll
        for (int ni = 0; ni < 8; ++ni)
            #pragma unroll
            for (int q = 0; q < 4; ++q) acc[mi][ni][q] = 0.f;

    // loader: A 128r x 4 chunks = 512 cp16 (4/thr); B 32r x 8 chunks = 256 (2/thr)
    const int t4 = tid * 4, t2 = tid * 2;
    auto issue = [&](int ch, int stg) {
        const uint32_t st = sb + (uint32_t)stg * G_STAGE;
        #pragma unroll
        for (int u = 0; u < 4; ++u) {
            const int ia = t4 + u;
            const int ar = ia >> 2, ac = ia & 3;
            cp16(st + G_A + (uint32_t)ar * 80 + ac * 16,
                 Ah + (size_t)(bm + ar) * K + ch * 32 + ac * 8);
        }
        #pragma unroll
        for (int u = 0; u < 2; ++u) {
            const int ib = t2 + u;
            const int br = ib >> 3, bc = ib & 7;
            cp16(st + G_B + (uint32_t)br * 144 + bc * 16,
                 Bh + (size_t)(ch * 32 + br) * N + bn + bc * 8);
        }
        CP_COMMIT();
    };

    const int nchunks = K / 32;
    issue(0, 0);
    issue(1, 1);

    for (int ch = 0; ch < nchunks; ++ch) {
        CP_WAIT(1);
        __syncthreads();
        if (ch + 2 < nchunks) issue(ch + 2, (ch + 2) % G_NSTAGE);
        else                  CP_COMMIT();

        const uint32_t st = sb + (uint32_t)(ch % G_NSTAGE) * G_STAGE;
        #pragma unroll
        for (int ks = 0; ks < 2; ++ks) {
            const int k0 = ks * 16;
            uint32_t aH[2][4];
            #pragma unroll
            for (int mi = 0; mi < 2; ++mi) {
                const uint32_t ao = (uint32_t)(a_r + mi * 16) * 80 + (k0 + a_c) * 2;
                ldsm_x4(aH[mi], st + G_A + ao);
            }
            #pragma unroll
            for (int j = 0; j < 4; ++j) {
                const uint32_t bo = (uint32_t)(k0 + b_row) * 144
                                  + (uint32_t)(j * 16) * 2 + b_colb;
                uint32_t bH[4];
                ldsm_x4_t(bH, st + G_B + bo);
                mma16816(acc[0][2 * j],     aH[0], bH[0], bH[1]);
                mma16816(acc[1][2 * j],     aH[1], bH[0], bH[1]);
                mma16816(acc[0][2 * j + 1], aH[0], bH[2], bH[3]);
                mma16816(acc[1][2 * j + 1], aH[1], bH[2], bH[3]);
            }
        }
    }

    const int g = lane >> 2, cpair = (lane & 3) * 2;
    #pragma unroll
    for (int mi = 0; mi < 2; ++mi) {
        #pragma unroll
        for (int ni = 0; ni < 8; ++ni) {
            const size_t r0 = (size_t)(bm + wm + mi * 16 + g) * N + bn + ni * 8 + cpair;
            const size_t r1 = r0 + (size_t)8 * N;
            if (HALF_OUT) {
                *(uint32_t*)(Ch + r0) = pkh2(acc[mi][ni][0], acc[mi][ni][1]);
                *(uint32_t*)(Ch + r1) = pkh2(acc[mi][ni][2], acc[mi][ni][3]);
            } else {
                *(float2*)(Cf + r0) = make_float2(acc[mi][ni][0], acc[mi][ni][1]);
                *(float2*)(Cf + r1) = make_float2(acc[mi][ni][2], acc[mi][ni][3]);
            }
        }
    }
}

// ---------------------------------------------------------------------------
// Flash-attention (unchanged R14): single-pass fp16, 3-stage cp.async,
// Q-tile 128, 256 thr, LPT heavy-first, log2-space softmax.
// ---------------------------------------------------------------------------
#define A_K 0
#define A_V 9216                      /* 64 rows * 144B */
#define A_STAGE 18432
#define A_NSTAGE 3
#define ATTN_SMEM (A_NSTAGE * A_STAGE)

__global__ __launch_bounds__(256, 2) void attn_mma(
    const __half* __restrict__ qkvh, __half* __restrict__ oh)
{
    extern __shared__ __align__(128) char smem[];
    const uint32_t sb = smem_u32(smem);

    const int bid = blockIdx.x;
    const int qt = (T_ / 128) - 1 - (bid >> 5);   // heavy first
    const int bh = bid & 31;
    const int b = bh >> 4, h = bh & 15;
    const int tid = threadIdx.x;
    const int wid = tid >> 5, lane = tid & 31;
    const int g = lane >> 2, c = lane & 3;
    const int wq = wid * 16;

    const float LOG2E = 1.4426950408889634f;
    const float scale2 = 0.125f * LOG2E;
    const float slope2 = exp2f(-0.5f * (float)(h + 1)) * LOG2E;

    const size_t bbase = (size_t)b * T_ * 3 * C_;
    const int i0 = qt * 128 + wq + g;
    const int i1 = i0 + 8;

    uint32_t qh[4][4];
    {
        const __half* q0 = qkvh + bbase + (size_t)i0 * (3 * C_) + h * D_;
        #pragma unroll
        for (int s = 0; s < 4; ++s) {
            const int k0 = s * 16 + 2 * c;
            qh[s][0] = *(const uint32_t*)(q0 + k0);
            qh[s][1] = *(const uint32_t*)(q0 + (size_t)8 * 3 * C_ + k0);
            qh[s][2] = *(const uint32_t*)(q0 + k0 + 8);
            qh[s][3] = *(const uint32_t*)(q0 + (size_t)8 * 3 * C_ + k0 + 8);
        }
    }

    const uint32_t k_row = (uint32_t)((lane >> 4) * 8 + (lane & 7));
    const uint32_t k_colb = (uint32_t)(((lane >> 3) & 1) * 8) * 2;
    const uint32_t v_row = (uint32_t)(((lane >> 3) & 1) * 8 + (lane & 7));
    const uint32_t v_colb = (uint32_t)((lane >> 4) * 8) * 2;

    float o[8][4];
    #pragma unroll
    for (int t = 0; t < 8; ++t)
        #pragma unroll
        for (int q = 0; q < 4; ++q) o[t][q] = 0.f;
    float m0 = -INFINITY, m1 = -INFINITY, l0 = 0.f, l1 = 0.f;

    const int jtmax = 2 * qt + 1;

    const int t2 = tid * 2;
    auto issue = [&](int jt, int stg) {
        const uint32_t st = sb + (uint32_t)stg * A_STAGE;
        #pragma unroll
        for (int u = 0; u < 2; ++u) {
            const int ia = t2 + u;
            const int row = ia >> 3, ch = ia & 7;
            const size_t go = bbase + (size_t)(jt * 64 + row) * (3 * C_) + h * D_ + ch * 8;
            const uint32_t so = (uint32_t)row * 144 + ch * 16;
            cp16(st + A_K + so, qkvh + go + C_);
            cp16(st + A_V + so, qkvh + go + 2 * C_);
        }
        CP_COMMIT();
    };

    issue(0, 0);
    issue(1, 1);

    for (int jt = 0; jt <= jtmax; ++jt) {
        CP_WAIT(1);
        __syncthreads();
        if (jt + 2 <= jtmax) issue(jt + 2, (jt + 2) % A_NSTAGE);
        else                 CP_COMMIT();

        const bool active = (jt * 64 <= qt * 128 + wq + 15);
        if (active) {
            const uint32_t st = sb + (uint32_t)(jt % A_NSTAGE) * A_STAGE;

            float sacc[8][4];
            #pragma unroll
            for (int t = 0; t < 8; ++t)
                #pragma unroll
                for (int q = 0; q < 4; ++q) sacc[t][q] = 0.f;

            #pragma unroll
            for (int s = 0; s < 4; ++s) {
                const uint32_t k0b = (uint32_t)(s * 16) * 2;
                #pragma unroll
                for (int np = 0; np < 4; ++np) {
                    const uint32_t off = (uint32_t)(np * 16 + k_row) * 144 + k0b + k_colb;
                    uint32_t bH[4];
                    ldsm_x4(bH, st + A_K + off);
                    mma16816(sacc[2 * np],     qh[s], bH[0], bH[1]);
                    mma16816(sacc[2 * np + 1], qh[s], bH[2], bH[3]);
                }
            }

            const bool needmask = (jt >= 2 * qt);
            #pragma unroll
            for (int t = 0; t < 8; ++t) {
                const int j0 = jt * 64 + t * 8 + 2 * c;
                sacc[t][0] = fmaf(sacc[t][0], scale2, slope2 * (float)(i0 - j0));
                sacc[t][1] = fmaf(sacc[t][1], scale2, slope2 * (float)(i0 - j0 - 1));
                sacc[t][2] = fmaf(sacc[t][2], scale2, slope2 * (float)(i1 - j0));
                sacc[t][3] = fmaf(sacc[t][3], scale2, slope2 * (float)(i1 - j0 - 1));
                if (needmask) {
                    if (j0     > i0) sacc[t][0] = -INFINITY;
                    if (j0 + 1 > i0) sacc[t][1] = -INFINITY;
                    if (j0     > i1) sacc[t][2] = -INFINITY;
                    if (j0 + 1 > i1) sacc[t][3] = -INFINITY;
                }
            }

            float rm0 = -INFINITY, rm1 = -INFINITY;
            #pragma unroll
            for (int t = 0; t < 8; ++t) {
                rm0 = fmaxf(rm0, fmaxf(sacc[t][0], sacc[t][1]));
                rm1 = fmaxf(rm1, fmaxf(sacc[t][2], sacc[t][3]));
            }
            rm0 = fmaxf(rm0, __shfl_xor_sync(0xffffffffu, rm0, 1));
            rm0 = fmaxf(rm0, __shfl_xor_sync(0xffffffffu, rm0, 2));
            rm1 = fmaxf(rm1, __shfl_xor_sync(0xffffffffu, rm1, 1));
            rm1 = fmaxf(rm1, __shfl_xor_sync(0xffffffffu, rm1, 2));
            const float mn0 = fmaxf(m0, rm0), mn1 = fmaxf(m1, rm1);
            const float c0 = exp2f(m0 - mn0), c1 = exp2f(m1 - mn1);
            m0 = mn0; m1 = mn1;

            uint32_t pA[8], pB[8];
            float s0 = 0.f, s1 = 0.f;
            #pragma unroll
            for (int t = 0; t < 8; ++t) {
                const float p0 = exp2f(sacc[t][0] - mn0);
                const float p1 = exp2f(sacc[t][1] - mn0);
                const float p2 = exp2f(sacc[t][2] - mn1);
                const float p3 = exp2f(sacc[t][3] - mn1);
                s0 += p0 + p1; s1 += p2 + p3;
                pA[t] = pkh2(p0, p1);
                pB[t] = pkh2(p2, p3);
            }
            l0 = l0 * c0 + s0;
            l1 = l1 * c1 + s1;
            #pragma unroll
            for (int t = 0; t < 8; ++t) {
                o[t][0] *= c0; o[t][1] *= c0;
                o[t][2] *= c1; o[t][3] *= c1;
            }

            #pragma unroll
            for (int s = 0; s < 4; ++s) {
                const uint32_t aH[4] = {pA[2 * s], pB[2 * s], pA[2 * s + 1], pB[2 * s + 1]};
                const uint32_t rowb = (uint32_t)(s * 16 + v_row) * 144;
                #pragma unroll
                for (int ng = 0; ng < 4; ++ng) {
                    const uint32_t off = rowb + (uint32_t)(ng * 16) * 2 + v_colb;
                    uint32_t vH[4];
                    ldsm_x4_t(vH, st + A_V + off);
                    mma16816(o[2 * ng],     aH, vH[0], vH[1]);
                    mma16816(o[2 * ng + 1], aH, vH[2], vH[3]);
                }
            }
        }
    }

    l0 += __shfl_xor_sync(0xffffffffu, l0, 1);
    l0 += __shfl_xor_sync(0xffffffffu, l0, 2);
    l1 += __shfl_xor_sync(0xffffffffu, l1, 1);
    l1 += __shfl_xor_sync(0xffffffffu, l1, 2);
    const float inv0 = 1.f / l0, inv1 = 1.f / l1;

    const size_t r0 = (size_t)(b * T_ + i0) * C_ + h * D_ + 2 * c;
    const size_t r1 = (size_t)(b * T_ + i1) * C_ + h * D_ + 2 * c;
    #pragma unroll
    for (int t = 0; t < 8; ++t) {
        *(uint32_t*)(oh + r0 + t * 8) = pkh2(o[t][0] * inv0, o[t][1] * inv0);
        *(uint32_t*)(oh + r1 + t * 8) = pkh2(o[t][2] * inv1, o[t][3] * inv1);
    }
}

// ---------------------------------------------------------------------------
extern "C" void kernel_launch(void* const* d_in, const int* in_sizes, int n_in,
                              void* d_out, int out_size)
{
    const float* x      = (const float*)d_in[0];  // [B,T,C]
    const float* w_qkv  = (const float*)d_in[1];  // [C,3C]
    const float* w_proj = (const float*)d_in[2];  // [C,C]
    float* out = (float*)d_out;                   // [B,T,C]

    __half *xh, *wqh, *wph, *qkvh, *ath;
    cudaGetSymbolAddress((void**)&xh, g_xh);
    cudaGetSymbolAddress((void**)&wqh, g_wqh);
    cudaGetSymbolAddress((void**)&wph, g_wph);
    cudaGetSymbolAddress((void**)&qkvh, g_qkvh);
    cudaGetSymbolAddress((void**)&ath, g_ath);

    cudaFuncSetAttribute(gemm_fp16<0>, cudaFuncAttributeMaxDynamicSharedMemorySize, GEMM_SMEM);
    cudaFuncSetAttribute(gemm_fp16<1>, cudaFuncAttributeMaxDynamicSharedMemorySize, GEMM_SMEM);
    cudaFuncSetAttribute(attn_mma, cudaFuncAttributeMaxDynamicSharedMemorySize, ATTN_SMEM);

    const int M = B_ * T_;  // 4096

    // 0) fused convert of all inputs to fp16
    const int n4_total = N4_X + N4_WQ + N4_WP;
    cvt_all_kernel<<<(n4_total + 255) / 256, 256>>>(x, w_qkv, w_proj, xh, wqh, wph);

    // 1) qkv = x @ w_qkv  -> fp16   (tile 128x64, 1536 CTAs)
    gemm_fp16<1><<<dim3((3 * C_) / 64, M / 128), 128, GEMM_SMEM>>>(
        xh, wqh, nullptr, qkvh, M, 3 * C_, C_);

    // 2) attention -> fp16  (Q-tile 128, 1D LPT grid: heavy CTAs first)
    attn_mma<<<(T_ / 128) * B_ * H_, 256, ATTN_SMEM>>>(qkvh, ath);

    // 3) out = att @ w_proj -> fp32  (tile 128x64, 512 CTAs)
    gemm_fp16<0><<<dim3(C_ / 64, M / 128), 128, GEMM_SMEM>>>(
        ath, wph, out, nullptr, M, C_, C_);
}

// round 16
// speedup vs baseline: 1.2566x; 1.2566x over previous
#include <cuda_runtime.h>
#include <cuda_fp16.h>
#include <math.h>
#include <stdint.h>

#define B_ 2
#define T_ 2048
#define C_ 1024
#define H_ 16
#define D_ 64

// ---------------- scratch (allocation-free rule: __device__ globals) --------
__device__ __half g_xh[(size_t)B_ * T_ * C_];
__device__ __half g_wqh[(size_t)C_ * 3 * C_];
__device__ __half g_wph[(size_t)C_ * C_];
__device__ __half g_qkvh[(size_t)B_ * T_ * 3 * C_];
__device__ __half g_ath[(size_t)B_ * T_ * C_];

// ---------------- helpers ----------------------------------------------------
__device__ __forceinline__ uint32_t smem_u32(const void* p) {
    uint32_t a;
    asm("{ .reg .u64 t; cvta.to.shared.u64 t, %1; cvt.u32.u64 %0, t; }"
        : "=r"(a) : "l"(p));
    return a;
}
__device__ __forceinline__ void ldsm_x4(uint32_t* r, uint32_t addr) {
    asm volatile("ldmatrix.sync.aligned.m8n8.x4.shared.b16 {%0,%1,%2,%3}, [%4];"
                 : "=r"(r[0]), "=r"(r[1]), "=r"(r[2]), "=r"(r[3]) : "r"(addr));
}
__device__ __forceinline__ void ldsm_x4_t(uint32_t* r, uint32_t addr) {
    asm volatile("ldmatrix.sync.aligned.m8n8.x4.trans.shared.b16 {%0,%1,%2,%3}, [%4];"
                 : "=r"(r[0]), "=r"(r[1]), "=r"(r[2]), "=r"(r[3]) : "r"(addr));
}
__device__ __forceinline__ void mma16816(float* d, const uint32_t* a,
                                         uint32_t b0, uint32_t b1) {
    asm volatile(
        "mma.sync.aligned.m16n8k16.row.col.f32.f16.f16.f32 "
        "{%0,%1,%2,%3}, {%4,%5,%6,%7}, {%8,%9}, {%0,%1,%2,%3};"
        : "+f"(d[0]), "+f"(d[1]), "+f"(d[2]), "+f"(d[3])
        : "r"(a[0]), "r"(a[1]), "r"(a[2]), "r"(a[3]), "r"(b0), "r"(b1));
}
__device__ __forceinline__ void cp16(uint32_t dst, const void* src) {
    asm volatile("cp.async.cg.shared.global [%0], [%1], 16;" :: "r"(dst), "l"(src));
}
#define CP_COMMIT() asm volatile("cp.async.commit_group;" ::: "memory")
#define CP_WAIT(n)  asm volatile("cp.async.wait_group %0;" :: "n"(n) : "memory")

__device__ __forceinline__ uint32_t pkh2(float a, float b) {
    __half2 t = __floats2half2_rn(a, b);
    return *reinterpret_cast<uint32_t*>(&t);
}

// ---------------- fused fp32 -> fp16 convert (x, w_qkv, w_proj) -------------
#define N4_X  (B_ * T_ * C_ / 4)
#define N4_WQ (C_ * 3 * C_ / 4)
#define N4_WP (C_ * C_ / 4)

__global__ __launch_bounds__(256) void cvt_all_kernel(
    const float* __restrict__ x, const float* __restrict__ wq,
    const float* __restrict__ wp, __half* __restrict__ xh,
    __half* __restrict__ wqh, __half* __restrict__ wph)
{
    int i = blockIdx.x * blockDim.x + threadIdx.x;
    const float* src;
    __half* dst;
    if (i < N4_X) { src = x; dst = xh; }
    else if (i < N4_X + N4_WQ) { i -= N4_X; src = wq; dst = wqh; }
    else { i -= N4_X + N4_WQ; src = wp; dst = wph; if (i >= N4_WP) return; }
    const float4 f = ((const float4*)src)[i];
    ((uint2*)dst)[i] = make_uint2(pkh2(f.x, f.y), pkh2(f.z, f.w));
}

// ---------------------------------------------------------------------------
// Single-pass fp16 GEMM (fp32 accum): C = A @ B. BK=32, 3-stage cp.async.
// 256 thr, 8 warps 4x2, warp tile 32x64, 2 CTAs/SM.  (proven config)
// ---------------------------------------------------------------------------
#define G_A  0
#define G_B  10240                    /* 128 rows * 80B */
#define G_STAGE 18944                 /* + 32 rows * 272B */
#define G_NSTAGE 3
#define GEMM_SMEM (G_NSTAGE * G_STAGE)

template<int HALF_OUT>
__global__ __launch_bounds__(256, 2) void gemm_fp16(
    const __half* __restrict__ Ah, const __half* __restrict__ Bh,
    float* __restrict__ Cf, __half* __restrict__ Ch, int M, int N, int K)
{
    extern __shared__ __align__(128) char smem[];
    const uint32_t sb = smem_u32(smem);

    const int tid = threadIdx.x;
    const int wid = tid >> 5, lane = tid & 31;
    const int bm = blockIdx.y * 128, bn = blockIdx.x * 128;
    const int wm = (wid >> 1) * 32;
    const int wn = (wid & 1) * 64;
    const int t2 = tid * 2;

    const int a_r = wm + (lane & 15);
    const int a_c = (lane >> 4) * 8;
    const uint32_t b_row = (uint32_t)(((lane >> 3) & 1) * 8 + (lane & 7));
    const uint32_t b_colb = (uint32_t)((lane >> 4) * 8) * 2;

    float acc[2][8][4];
    #pragma unroll
    for (int mi = 0; mi < 2; ++mi)
        #pragma unroll
        for (int ni = 0; ni < 8; ++ni)
            #pragma unroll
            for (int q = 0; q < 4; ++q) acc[mi][ni][q] = 0.f;

    auto issue = [&](int ch, int stg) {
        const uint32_t st = sb + (uint32_t)stg * G_STAGE;
        #pragma unroll
        for (int u = 0; u < 2; ++u) {
            const int ia = t2 + u;
            const int ar = ia >> 2, ac = ia & 3;
            cp16(st + G_A + (uint32_t)ar * 80 + ac * 16,
                 Ah + (size_t)(bm + ar) * K + ch * 32 + ac * 8);
            const int br = ia >> 4, bc = ia & 15;
            cp16(st + G_B + (uint32_t)br * 272 + bc * 16,
                 Bh + (size_t)(ch * 32 + br) * N + bn + bc * 8);
        }
        CP_COMMIT();
    };

    const int nchunks = K / 32;
    issue(0, 0);
    issue(1, 1);

    for (int ch = 0; ch < nchunks; ++ch) {
        CP_WAIT(1);
        __syncthreads();
        if (ch + 2 < nchunks) issue(ch + 2, (ch + 2) % G_NSTAGE);
        else                  CP_COMMIT();

        const uint32_t st = sb + (uint32_t)(ch % G_NSTAGE) * G_STAGE;
        #pragma unroll
        for (int ks = 0; ks < 2; ++ks) {
            const int k0 = ks * 16;
            uint32_t aH[2][4];
            #pragma unroll
            for (int mi = 0; mi < 2; ++mi) {
                const uint32_t ao = (uint32_t)(a_r + mi * 16) * 80 + (k0 + a_c) * 2;
                ldsm_x4(aH[mi], st + G_A + ao);
            }
            #pragma unroll
            for (int j = 0; j < 4; ++j) {
                const uint32_t bo = (uint32_t)(k0 + b_row) * 272
                                  + (uint32_t)(wn + j * 16) * 2 + b_colb;
                uint32_t bH[4];
                ldsm_x4_t(bH, st + G_B + bo);
                mma16816(acc[0][2 * j],     aH[0], bH[0], bH[1]);
                mma16816(acc[1][2 * j],     aH[1], bH[0], bH[1]);
                mma16816(acc[0][2 * j + 1], aH[0], bH[2], bH[3]);
                mma16816(acc[1][2 * j + 1], aH[1], bH[2], bH[3]);
            }
        }
    }

    const int g = lane >> 2, cpair = (lane & 3) * 2;
    #pragma unroll
    for (int mi = 0; mi < 2; ++mi) {
        #pragma unroll
        for (int ni = 0; ni < 8; ++ni) {
            const size_t r0 = (size_t)(bm + wm + mi * 16 + g) * N + bn + wn + ni * 8 + cpair;
            const size_t r1 = r0 + (size_t)8 * N;
            if (HALF_OUT) {
                *(uint32_t*)(Ch + r0) = pkh2(acc[mi][ni][0], acc[mi][ni][1]);
                *(uint32_t*)(Ch + r1) = pkh2(acc[mi][ni][2], acc[mi][ni][3]);
            } else {
                *(float2*)(Cf + r0) = make_float2(acc[mi][ni][0], acc[mi][ni][1]);
                *(float2*)(Cf + r1) = make_float2(acc[mi][ni][2], acc[mi][ni][3]);
            }
        }
    }
}

// ---------------------------------------------------------------------------
// Flash-attention, single-pass fp16 (fp32 accum), 3-stage cp.async.
// Q-tile 128, 256 thr, LPT heavy-first, log2-space softmax. (R14 proven)
// ---------------------------------------------------------------------------
#define A_K 0
#define A_V 9216                      /* 64 rows * 144B */
#define A_STAGE 18432
#define A_NSTAGE 3
#define ATTN_SMEM (A_NSTAGE * A_STAGE)

__global__ __launch_bounds__(256, 2) void attn_mma(
    const __half* __restrict__ qkvh, __half* __restrict__ oh)
{
    extern __shared__ __align__(128) char smem[];
    const uint32_t sb = smem_u32(smem);

    const int bid = blockIdx.x;
    const int qt = (T_ / 128) - 1 - (bid >> 5);   // heavy first
    const int bh = bid & 31;
    const int b = bh >> 4, h = bh & 15;
    const int tid = threadIdx.x;
    const int wid = tid >> 5, lane = tid & 31;
    const int g = lane >> 2, c = lane & 3;
    const int wq = wid * 16;

    const float LOG2E = 1.4426950408889634f;
    const float scale2 = 0.125f * LOG2E;
    const float slope2 = exp2f(-0.5f * (float)(h + 1)) * LOG2E;

    const size_t bbase = (size_t)b * T_ * 3 * C_;
    const int i0 = qt * 128 + wq + g;
    const int i1 = i0 + 8;

    uint32_t qh[4][4];
    {
        const __half* q0 = qkvh + bbase + (size_t)i0 * (3 * C_) + h * D_;
        #pragma unroll
        for (int s = 0; s < 4; ++s) {
            const int k0 = s * 16 + 2 * c;
            qh[s][0] = *(const uint32_t*)(q0 + k0);
            qh[s][1] = *(const uint32_t*)(q0 + (size_t)8 * 3 * C_ + k0);
            qh[s][2] = *(const uint32_t*)(q0 + k0 + 8);
            qh[s][3] = *(const uint32_t*)(q0 + (size_t)8 * 3 * C_ + k0 + 8);
        }
    }

    const uint32_t k_row = (uint32_t)((lane >> 4) * 8 + (lane & 7));
    const uint32_t k_colb = (uint32_t)(((lane >> 3) & 1) * 8) * 2;
    const uint32_t v_row = (uint32_t)(((lane >> 3) & 1) * 8 + (lane & 7));
    const uint32_t v_colb = (uint32_t)((lane >> 4) * 8) * 2;

    float o[8][4];
    #pragma unroll
    for (int t = 0; t < 8; ++t)
        #pragma unroll
        for (int q = 0; q < 4; ++q) o[t][q] = 0.f;
    float m0 = -INFINITY, m1 = -INFINITY, l0 = 0.f, l1 = 0.f;

    const int jtmax = 2 * qt + 1;

    const int t2 = tid * 2;
    auto issue = [&](int jt, int stg) {
        const uint32_t st = sb + (uint32_t)stg * A_STAGE;
        #pragma unroll
        for (int u = 0; u < 2; ++u) {
            const int ia = t2 + u;
            const int row = ia >> 3, ch = ia & 7;
            const size_t go = bbase + (size_t)(jt * 64 + row) * (3 * C_) + h * D_ + ch * 8;
            const uint32_t so = (uint32_t)row * 144 + ch * 16;
            cp16(st + A_K + so, qkvh + go + C_);
            cp16(st + A_V + so, qkvh + go + 2 * C_);
        }
        CP_COMMIT();
    };

    issue(0, 0);
    issue(1, 1);

    for (int jt = 0; jt <= jtmax; ++jt) {
        CP_WAIT(1);
        __syncthreads();
        if (jt + 2 <= jtmax) issue(jt + 2, (jt + 2) % A_NSTAGE);
        else                 CP_COMMIT();

        const bool active = (jt * 64 <= qt * 128 + wq + 15);
        if (active) {
            const uint32_t st = sb + (uint32_t)(jt % A_NSTAGE) * A_STAGE;

            float sacc[8][4];
            #pragma unroll
            for (int t = 0; t < 8; ++t)
                #pragma unroll
                for (int q = 0; q < 4; ++q) sacc[t][q] = 0.f;

            #pragma unroll
            for (int s = 0; s < 4; ++s) {
                const uint32_t k0b = (uint32_t)(s * 16) * 2;
                #pragma unroll
                for (int np = 0; np < 4; ++np) {
                    const uint32_t off = (uint32_t)(np * 16 + k_row) * 144 + k0b + k_colb;
                    uint32_t bH[4];
                    ldsm_x4(bH, st + A_K + off);
                    mma16816(sacc[2 * np],     qh[s], bH[0], bH[1]);
                    mma16816(sacc[2 * np + 1], qh[s], bH[2], bH[3]);
                }
            }

            const bool needmask = (jt >= 2 * qt);
            #pragma unroll
            for (int t = 0; t < 8; ++t) {
                const int j0 = jt * 64 + t * 8 + 2 * c;
                sacc[t][0] = fmaf(sacc[t][0], scale2, slope2 * (float)(i0 - j0));
                sacc[t][1] = fmaf(sacc[t][1], scale2, slope2 * (float)(i0 - j0 - 1));
                sacc[t][2] = fmaf(sacc[t][2], scale2, slope2 * (float)(i1 - j0));
                sacc[t][3] = fmaf(sacc[t][3], scale2, slope2 * (float)(i1 - j0 - 1));
                if (needmask) {
                    if (j0     > i0) sacc[t][0] = -INFINITY;
                    if (j0 + 1 > i0) sacc[t][1] = -INFINITY;
                    if (j0     > i1) sacc[t][2] = -INFINITY;
                    if (j0 + 1 > i1) sacc[t][3] = -INFINITY;
                }
            }

            float rm0 = -INFINITY, rm1 = -INFINITY;
            #pragma unroll
            for (int t = 0; t < 8; ++t) {
                rm0 = fmaxf(rm0, fmaxf(sacc[t][0], sacc[t][1]));
                rm1 = fmaxf(rm1, fmaxf(sacc[t][2], sacc[t][3]));
            }
            rm0 = fmaxf(rm0, __shfl_xor_sync(0xffffffffu, rm0, 1));
            rm0 = fmaxf(rm0, __shfl_xor_sync(0xffffffffu, rm0, 2));
            rm1 = fmaxf(rm1, __shfl_xor_sync(0xffffffffu, rm1, 1));
            rm1 = fmaxf(rm1, __shfl_xor_sync(0xffffffffu, rm1, 2));
            const float mn0 = fmaxf(m0, rm0), mn1 = fmaxf(m1, rm1);
            const float c0 = exp2f(m0 - mn0), c1 = exp2f(m1 - mn1);
            m0 = mn0; m1 = mn1;

            uint32_t pA[8], pB[8];
            float s0 = 0.f, s1 = 0.f;
            #pragma unroll
            for (int t = 0; t < 8; ++t) {
                const float p0 = exp2f(sacc[t][0] - mn0);
                const float p1 = exp2f(sacc[t][1] - mn0);
                const float p2 = exp2f(sacc[t][2] - mn1);
                const float p3 = exp2f(sacc[t][3] - mn1);
                s0 += p0 + p1; s1 += p2 + p3;
                pA[t] = pkh2(p0, p1);
                pB[t] = pkh2(p2, p3);
            }
            l0 = l0 * c0 + s0;
            l1 = l1 * c1 + s1;
            #pragma unroll
            for (int t = 0; t < 8; ++t) {
                o[t][0] *= c0; o[t][1] *= c0;
                o[t][2] *= c1; o[t][3] *= c1;
            }

            #pragma unroll
            for (int s = 0; s < 4; ++s) {
                const uint32_t aH[4] = {pA[2 * s], pB[2 * s], pA[2 * s + 1], pB[2 * s + 1]};
                const uint32_t rowb = (uint32_t)(s * 16 + v_row) * 144;
                #pragma unroll
                for (int ng = 0; ng < 4; ++ng) {
                    const uint32_t off = rowb + (uint32_t)(ng * 16) * 2 + v_colb;
                    uint32_t vH[4];
                    ldsm_x4_t(vH, st + A_V + off);
                    mma16816(o[2 * ng],     aH, vH[0], vH[1]);
                    mma16816(o[2 * ng + 1], aH, vH[2], vH[3]);
                }
            }
        }
    }

    l0 += __shfl_xor_sync(0xffffffffu, l0, 1);
    l0 += __shfl_xor_sync(0xffffffffu, l0, 2);
    l1 += __shfl_xor_sync(0xffffffffu, l1, 1);
    l1 += __shfl_xor_sync(0xffffffffu, l1, 2);
    const float inv0 = 1.f / l0, inv1 = 1.f / l1;

    const size_t r0 = (size_t)(b * T_ + i0) * C_ + h * D_ + 2 * c;
    const size_t r1 = (size_t)(b * T_ + i1) * C_ + h * D_ + 2 * c;
    #pragma unroll
    for (int t = 0; t < 8; ++t) {
        *(uint32_t*)(oh + r0 + t * 8) = pkh2(o[t][0] * inv0, o[t][1] * inv0);
        *(uint32_t*)(oh + r1 + t * 8) = pkh2(o[t][2] * inv1, o[t][3] * inv1);
    }
}

// ---------------------------------------------------------------------------
extern "C" void kernel_launch(void* const* d_in, const int* in_sizes, int n_in,
                              void* d_out, int out_size)
{
    const float* x      = (const float*)d_in[0];  // [B,T,C]
    const float* w_qkv  = (const float*)d_in[1];  // [C,3C]
    const float* w_proj = (const float*)d_in[2];  // [C,C]
    float* out = (float*)d_out;                   // [B,T,C]

    __half *xh, *wqh, *wph, *qkvh, *ath;
    cudaGetSymbolAddress((void**)&xh, g_xh);
    cudaGetSymbolAddress((void**)&wqh, g_wqh);
    cudaGetSymbolAddress((void**)&wph, g_wph);
    cudaGetSymbolAddress((void**)&qkvh, g_qkvh);
    cudaGetSymbolAddress((void**)&ath, g_ath);

    cudaFuncSetAttribute(gemm_fp16<0>, cudaFuncAttributeMaxDynamicSharedMemorySize, GEMM_SMEM);
    cudaFuncSetAttribute(gemm_fp16<1>, cudaFuncAttributeMaxDynamicSharedMemorySize, GEMM_SMEM);
    cudaFuncSetAttribute(attn_mma, cudaFuncAttributeMaxDynamicSharedMemorySize, ATTN_SMEM);

    const int M = B_ * T_;  // 4096

    // 0) fused convert of all inputs to fp16
    const int n4_total = N4_X + N4_WQ + N4_WP;
    cvt_all_kernel<<<(n4_total + 255) / 256, 256>>>(x, w_qkv, w_proj, xh, wqh, wph);

    // 1) qkv = x @ w_qkv  -> fp16
    gemm_fp16<1><<<dim3((3 * C_) / 128, M / 128), 256, GEMM_SMEM>>>(
        xh, wqh, nullptr, qkvh, M, 3 * C_, C_);

    // 2) attention -> fp16  (Q-tile 128, 1D LPT grid: heavy CTAs first)
    attn_mma<<<(T_ / 128) * B_ * H_, 256, ATTN_SMEM>>>(qkvh, ath);

    // 3) out = att @ w_proj -> fp32
    gemm_fp16<0><<<dim3(C_ / 128, M / 128), 256, GEMM_SMEM>>>(
        ath, wph, out, nullptr, M, C_, C_);
}